// round 17
// baseline (speedup 1.0000x reference)
#include <cuda_runtime.h>
#include <cuda_fp16.h>
#include <cstdint>

// SegmentMM: out[i] = A[i] @ B_eff[segA[i]]
// A:[131072,64] f32, B:[128,64,64] f32, segA int32 sorted, segB int32 perm.
// R17 = R16 (fp16 single-product HMMA, 32x32 warp tile, permuted-B float4
// epilogue) + __launch_bounds__(128, 8): force 64 regs -> 8 CTA/SM
// (32 warps vs 24). Identical instruction stream otherwise.

#define S_SEG 128

// Pre-converted B: fp16, SW128-swizzled, COLUMN-PERMUTED (by segment label).
// Permutation: global col 16p+4q+j ->
//   j=0,1 -> ntile 2p   cols 2q,2q+1   (byte unit 8p+q)
//   j=2,3 -> ntile 2p+1 cols 2q,2q+1   (byte unit 8p+q+4)
__device__ __align__(16) unsigned char d_Bf[S_SEG * 8192];

__device__ __forceinline__ uint32_t sw128(uint32_t off) {
    return off ^ ((off >> 3) & 0x70);
}

__device__ __forceinline__ uint2 cvt_h4(float4 v) {
    __half2 h01 = __floats2half2_rn(v.x, v.y);
    __half2 h23 = __floats2half2_rn(v.z, v.w);
    return make_uint2(*(uint32_t*)&h01, *(uint32_t*)&h23);
}

// ---- B pre-convert kernel: fp16 + column-permute + swizzle ----
__global__ __launch_bounds__(256)
void preconv_B_kernel(const float* __restrict__ B,
                      const int* __restrict__ segB)
{
    const int j = blockIdx.x;
    const int s = segB[j];
    const int tid = threadIdx.x;
    const float4* B4 = (const float4*)(B + (size_t)j * 4096);
    unsigned char* bf = d_Bf + (size_t)s * 8192;
    #pragma unroll
    for (int it = 0; it < 4; ++it) {
        int i = it * 256 + tid;          // 0..1023 float4s
        float4 v = B4[i];
        int k = i >> 4, mq = i & 15;     // row k, cols 4mq..4mq+3
        int p = mq >> 2, q = mq & 3;
        uint32_t off0 = (uint32_t)(k * 128 + (8 * p + q) * 4);
        uint2 h = cvt_h4(v);
        *(uint32_t*)(bf + sw128(off0))      = h.x;
        *(uint32_t*)(bf + sw128(off0 + 16)) = h.y;
    }
}

// ---- main kernel smem: A fp16 8KB + B fp16 8KB ----
#define SM_A 0
#define SM_B 8192
#define SMEM_TOTAL 16384

__device__ __forceinline__ uint32_t smem_u32(const void* p) {
    uint32_t a;
    asm("{ .reg .u64 t; cvta.to.shared.u64 t, %1; cvt.u32.u64 %0, t; }"
        : "=r"(a) : "l"(p));
    return a;
}
__device__ __forceinline__ void ldsm_x4(uint32_t& r0, uint32_t& r1,
                                        uint32_t& r2, uint32_t& r3, uint32_t a) {
    asm volatile("ldmatrix.sync.aligned.m8n8.x4.shared.b16 {%0,%1,%2,%3}, [%4];"
                 : "=r"(r0), "=r"(r1), "=r"(r2), "=r"(r3) : "r"(a));
}
__device__ __forceinline__ void ldsm_x4t(uint32_t& r0, uint32_t& r1,
                                         uint32_t& r2, uint32_t& r3, uint32_t a) {
    asm volatile("ldmatrix.sync.aligned.m8n8.x4.trans.shared.b16 {%0,%1,%2,%3}, [%4];"
                 : "=r"(r0), "=r"(r1), "=r"(r2), "=r"(r3) : "r"(a));
}
__device__ __forceinline__ void mma16816(float* d, const uint32_t* a,
                                         uint32_t b0, uint32_t b1) {
    asm volatile(
        "mma.sync.aligned.m16n8k16.row.col.f32.f16.f16.f32 "
        "{%0,%1,%2,%3}, {%4,%5,%6,%7}, {%8,%9}, {%0,%1,%2,%3};"
        : "+f"(d[0]), "+f"(d[1]), "+f"(d[2]), "+f"(d[3])
        : "r"(a[0]), "r"(a[1]), "r"(a[2]), "r"(a[3]), "r"(b0), "r"(b1));
}
#define CP_ASYNC16(dst, src)                                                   \
    asm volatile("cp.async.cg.shared.global [%0], [%1], 16;"                   \
                 :: "r"(dst), "l"(src) : "memory")
#define CP_COMMIT  asm volatile("cp.async.commit_group;" ::: "memory")
#define CP_WAIT0   asm volatile("cp.async.wait_group 0;" ::: "memory")

__global__ __launch_bounds__(128, 8)
void segmm_hmma_kernel(const float* __restrict__ A,
                       const int* __restrict__ segA,
                       float* __restrict__ out)
{
    __shared__ __align__(128) unsigned char smem[SMEM_TOTAL];
    const uint32_t sb  = smem_u32(smem);
    const int tid  = threadIdx.x;
    const int w    = tid >> 5;
    const int lane = tid & 31;
    const int r0   = blockIdx.x * 64;

    // warp tile: rows wrow..wrow+31, cols whalf*32..+31
    const int wrow  = (w & 1) * 32;
    const int whalf = (w >> 1);

    const int rA = wrow + (lane >> 2);       // mtile0 rows rA, rA+8
    const int cq = (lane & 3) * 4;           // contiguous 4-col base (permuted)
    const int seg0 = segA[r0 + rA];
    const int seg1 = segA[r0 + rA + 8];
    const int seg2 = segA[r0 + rA + 16];     // mtile1 rows
    const int seg3 = segA[r0 + rA + 24];
    const int s_lo = segA[r0];
    const int s_hi = segA[r0 + 63];

    // ---- issue B(s_lo) cp.async FIRST (flies under the A phase) ----
    {
        const unsigned char* gb = d_Bf + (size_t)s_lo * 8192;
        #pragma unroll
        for (int it = 0; it < 4; ++it) {
            uint32_t off = (uint32_t)(it * 128 + tid) * 16;
            CP_ASYNC16(sb + SM_B + off, gb + off);
        }
        CP_COMMIT;
    }

    // ---- convert A tile (64x64 f32) -> fp16 SW128 smem ----
    {
        const float4* A4 = (const float4*)(A + (size_t)r0 * 64);
        #pragma unroll
        for (int it = 0; it < 8; ++it) {
            int i = it * 128 + tid;          // 0..1023 float4s
            float4 v = A4[i];
            int r = i >> 4, kq = i & 15;
            uint32_t sw = sw128((uint32_t)(r * 128 + kq * 8));
            *(uint2*)(smem + SM_A + sw) = cvt_h4(v);
        }
    }
    CP_WAIT0;
    __syncthreads();

    const uint32_t a_row = (uint32_t)(wrow + (lane & 15));   // mtile0 ldsm row
    const uint32_t a_sel = (uint32_t)(lane >> 4) * 16;
    const uint32_t b_row = (uint32_t)(lane & 15);
    const uint32_t b_nt  = (uint32_t)(lane >> 4);            // 0 or 1

    for (int s = s_lo; s <= s_hi; ++s) {
        if (s > s_lo) {
            __syncthreads();   // everyone done reading previous B
            const unsigned char* gb = d_Bf + (size_t)s * 8192;
            #pragma unroll
            for (int it = 0; it < 4; ++it) {
                uint32_t off = (uint32_t)(it * 128 + tid) * 16;
                CP_ASYNC16(sb + SM_B + off, gb + off);
            }
            CP_COMMIT;
            CP_WAIT0;
            __syncthreads();
        }

        bool ok0 = (seg0 == s), ok1 = (seg1 == s);
        bool ok2 = (seg2 == s), ok3 = (seg3 == s);
        if (__ballot_sync(0xffffffffu, ok0 || ok1 || ok2 || ok3) == 0u) continue;

        float acc[2][4][4];                  // [mtile][ntile_local][frag]
        #pragma unroll
        for (int m = 0; m < 2; ++m)
            #pragma unroll
            for (int nt = 0; nt < 4; ++nt)
                #pragma unroll
                for (int q = 0; q < 4; ++q) acc[m][nt][q] = 0.f;

        #pragma unroll
        for (int kk = 0; kk < 4; ++kk) {
            // A fragments for both mtiles (sw128 commutes with +2048: bit11)
            uint32_t asw0 = sw128(a_row * 128 + (uint32_t)(kk * 32) + a_sel);
            uint32_t asw1 = asw0 + 16 * 128;
            uint32_t a0[4], a1[4];
            ldsm_x4(a0[0], a0[1], a0[2], a0[3], sb + SM_A + asw0);
            ldsm_x4(a1[0], a1[1], a1[2], a1[3], sb + SM_A + asw1);

            uint32_t roff = ((uint32_t)(kk * 16) + b_row) * 128;
            #pragma unroll
            for (int pl = 0; pl < 2; ++pl) {    // ntile-pair within half
                uint32_t cu = ((uint32_t)(whalf * 2 + pl) * 2 + b_nt) * 16;
                uint32_t sw = sw128(roff + cu);
                uint32_t b0, b1, b2, b3;
                ldsm_x4t(b0, b1, b2, b3, sb + SM_B + sw);
                mma16816(acc[0][pl * 2],     a0, b0, b1);
                mma16816(acc[0][pl * 2 + 1], a0, b2, b3);
                mma16816(acc[1][pl * 2],     a1, b0, b1);
                mma16816(acc[1][pl * 2 + 1], a1, b2, b3);
            }
        }

        // ---- contiguous float4 epilogue (permuted cols) ----
        #pragma unroll
        for (int m = 0; m < 2; ++m) {
            float* oA = out + (size_t)(r0 + rA + m * 16) * 64;
            float* oB = oA + (size_t)8 * 64;
            bool okAm = m ? ok2 : ok0;
            bool okBm = m ? ok3 : ok1;
            #pragma unroll
            for (int pl = 0; pl < 2; ++pl) {
                int col = 16 * (whalf * 2 + pl) + cq;
                if (okAm) *(float4*)(oA + col) =
                    make_float4(acc[m][2 * pl][0], acc[m][2 * pl][1],
                                acc[m][2 * pl + 1][0], acc[m][2 * pl + 1][1]);
                if (okBm) *(float4*)(oB + col) =
                    make_float4(acc[m][2 * pl][2], acc[m][2 * pl][3],
                                acc[m][2 * pl + 1][2], acc[m][2 * pl + 1][3]);
            }
        }
    }
}

extern "C" void kernel_launch(void* const* d_in, const int* in_sizes, int n_in,
                              void* d_out, int out_size) {
    const float* A    = (const float*)d_in[0];
    const float* B    = (const float*)d_in[1];
    const int*   segA = (const int*)d_in[2];
    const int*   segB = (const int*)d_in[3];
    float* out = (float*)d_out;

    const int N = in_sizes[0] / 64;      // 131072
    const int S = in_sizes[3];           // 128

    preconv_B_kernel<<<S, 256>>>(B, segB);
    segmm_hmma_kernel<<<N / 64, 128>>>(A, segA, out);
}